// round 5
// baseline (speedup 1.0000x reference)
#include <cuda_runtime.h>
#include <cuda_bf16.h>
#include <mma.h>

using namespace nvcuda;

// Problem constants
#define B_  2
#define T_  2048
#define C_  1024
#define H_  16
#define HD  64

// Scratch (device globals: allocation-free per harness rules)
__device__ float g_q[(size_t)B_ * H_ * T_ * HD];   // (b,h,t,d)
__device__ float g_k[(size_t)B_ * H_ * T_ * HD];
__device__ float g_v[(size_t)B_ * H_ * T_ * HD];
__device__ float g_att[(size_t)B_ * T_ * C_];      // (b,t,h*hd)

// ---------------------------------------------------------------------------
// GEMM: C[M,N] = A[M,K] @ W[K,N] + bias[N]
// BM=128, BN=128, BK=32, 256 threads (8 warps, 4x2 grid, 32x64 per warp)
// tf32 WMMA m16n16k8, fp32 accumulate. Register-prefetch double buffering.
// mode 0: write row-major to out.  mode 1: scatter into g_q/g_k/g_v.
// A == nullptr means "read from g_att" (output projection input).
// ---------------------------------------------------------------------------
#define GEMM_SMEM_BYTES (128 * 136 * 4)  // Cs epilogue dominates (As+Bs = 37888)

__global__ __launch_bounds__(256) void gemm_kernel(
    const float* __restrict__ Ain,
    const float* __restrict__ W,
    const float* __restrict__ bias,
    float* __restrict__ out,
    int N, int K, int mode)
{
    extern __shared__ float smem[];
    float* As = smem;               // 128 x 40 (tf32)
    float* Bs = smem + 128 * 40;    // 32 x 136 (tf32)
    float* Cs = smem;               // reuse: 128 x 136 (fp32) for epilogue

    const float* A = (Ain == nullptr) ? g_att : Ain;

    const int m0 = blockIdx.y * 128;
    const int n0 = blockIdx.x * 128;
    const int tid = threadIdx.x;
    const int warpId = tid >> 5;
    const int wr = warpId & 3;      // warp row (0..3) -> 32 rows each
    const int wc = warpId >> 2;     // warp col (0..1) -> 64 cols each

    // Per-thread load coordinates
    const int ar = tid >> 3;            // 0..31  (A row, step +32 per i)
    const int ac = (tid & 7) * 4;       // 0..28
    const int br = tid >> 5;            // 0..7   (B row, step +8 per i)
    const int bc = (tid & 31) * 4;      // 0..124

    wmma::fragment<wmma::accumulator, 16, 16, 8, float> acc[2][4];
#pragma unroll
    for (int i = 0; i < 2; i++)
#pragma unroll
        for (int j = 0; j < 4; j++)
            wmma::fill_fragment(acc[i][j], 0.0f);

    float4 aReg[4];
    float4 bReg[4];

    // Preload first K-tile into registers
#pragma unroll
    for (int i = 0; i < 4; i++)
        aReg[i] = *reinterpret_cast<const float4*>(
            &A[(size_t)(m0 + ar + i * 32) * K + 0 + ac]);
#pragma unroll
    for (int i = 0; i < 4; i++)
        bReg[i] = *reinterpret_cast<const float4*>(
            &W[(size_t)(0 + br + i * 8) * N + n0 + bc]);

    for (int k0 = 0; k0 < K; k0 += 32) {
        // Commit prefetched registers to shared (with RN tf32 conversion)
#pragma unroll
        for (int i = 0; i < 4; i++) {
            int r = ar + i * 32;
            As[r * 40 + ac + 0] = wmma::__float_to_tf32(aReg[i].x);
            As[r * 40 + ac + 1] = wmma::__float_to_tf32(aReg[i].y);
            As[r * 40 + ac + 2] = wmma::__float_to_tf32(aReg[i].z);
            As[r * 40 + ac + 3] = wmma::__float_to_tf32(aReg[i].w);
        }
#pragma unroll
        for (int i = 0; i < 4; i++) {
            int r = br + i * 8;
            Bs[r * 136 + bc + 0] = wmma::__float_to_tf32(bReg[i].x);
            Bs[r * 136 + bc + 1] = wmma::__float_to_tf32(bReg[i].y);
            Bs[r * 136 + bc + 2] = wmma::__float_to_tf32(bReg[i].z);
            Bs[r * 136 + bc + 3] = wmma::__float_to_tf32(bReg[i].w);
        }
        __syncthreads();

        // Prefetch next K-tile (overlaps with MMA below)
        if (k0 + 32 < K) {
#pragma unroll
            for (int i = 0; i < 4; i++)
                aReg[i] = *reinterpret_cast<const float4*>(
                    &A[(size_t)(m0 + ar + i * 32) * K + (k0 + 32) + ac]);
#pragma unroll
            for (int i = 0; i < 4; i++)
                bReg[i] = *reinterpret_cast<const float4*>(
                    &W[(size_t)(k0 + 32 + br + i * 8) * N + n0 + bc]);
        }

#pragma unroll
        for (int kk = 0; kk < 4; kk++) {
            wmma::fragment<wmma::matrix_a, 16, 16, 8, wmma::precision::tf32, wmma::row_major> af[2];
            wmma::fragment<wmma::matrix_b, 16, 16, 8, wmma::precision::tf32, wmma::row_major> bf[4];
#pragma unroll
            for (int i = 0; i < 2; i++)
                wmma::load_matrix_sync(af[i], &As[(wr * 32 + i * 16) * 40 + kk * 8], 40);
#pragma unroll
            for (int j = 0; j < 4; j++)
                wmma::load_matrix_sync(bf[j], &Bs[(kk * 8) * 136 + wc * 64 + j * 16], 136);
#pragma unroll
            for (int i = 0; i < 2; i++)
#pragma unroll
                for (int j = 0; j < 4; j++)
                    wmma::mma_sync(acc[i][j], af[i], bf[j], acc[i][j]);
        }
        __syncthreads();
    }

    // Epilogue: stage accumulators in shared, then SIMT write with bias.
#pragma unroll
    for (int i = 0; i < 2; i++)
#pragma unroll
        for (int j = 0; j < 4; j++)
            wmma::store_matrix_sync(&Cs[(wr * 32 + i * 16) * 136 + wc * 64 + j * 16],
                                    acc[i][j], 136, wmma::mem_row_major);
    __syncthreads();

    if (mode == 0) {
#pragma unroll
        for (int i = 0; i < 64; i++) {
            int slot = tid + i * 256;   // 0..16383
            int r = slot >> 7;          // 0..127
            int c = slot & 127;         // 0..127
            out[(size_t)(m0 + r) * N + n0 + c] = Cs[r * 136 + c] + bias[n0 + c];
        }
    } else {
        // QKV scatter. Column n = n0 + c; head period is 192 cols, so a
        // 128-col block can straddle heads: compute h/sel/d per element.
#pragma unroll
        for (int i = 0; i < 64; i++) {
            int slot = tid + i * 256;
            int r = slot >> 7;
            int c = slot & 127;
            int n = n0 + c;
            int h = n / 192;
            int rem = n - h * 192;
            int sel = rem >> 6;         // 0=q, 1=k, 2=v
            int d = rem & 63;
            float* dst = (sel == 0) ? g_q : (sel == 1) ? g_k : g_v;
            int m = m0 + r;
            int b = m >> 11;            // /T_
            int t = m & (T_ - 1);
            dst[(((size_t)(b * H_ + h)) * T_ + t) * HD + d] =
                Cs[r * 136 + c] + bias[n];
        }
    }
}

// ---------------------------------------------------------------------------
// Flash attention, FA2-style warp autonomy, register-resident O.
// CTA: 128 query rows for one (b,h); 8 warps, warp w owns rows [16w, 16w+16).
// Q persistent in matrix_a fragments (pre-scaled by 1/sqrt(hd)).
// O persistent in accumulator fragments; per-row alpha/inv applied via a
// one-time row-index discovery fragment + shfl (no layout assumptions).
// K/V tiles (64 keys) double-buffered in SMEM; K prefetched at tile start,
// V mid-tile. ONE __syncthreads per key tile. SMEM = 110592 B -> 2 CTA/SM.
// ---------------------------------------------------------------------------
#define ATTN_SMEM_BYTES ((128 * 72 + 2 * 64 * 72 + 2 * 64 * 72) * 4)  // 110592

__global__ __launch_bounds__(256, 2) void attn_kernel()
{
    extern __shared__ float smem[];
    float* Ss = smem;                    // 128 x 72: Q staging, then S/P (warp-private rows)
    float* Kb = Ss + 128 * 72;           // 2 x 64 x 72 (key tiles, tf32)
    float* Vb = Kb + 2 * 64 * 72;        // 2 x 64 x 72 (value tiles, tf32)

    // Reverse order: heaviest query tiles scheduled first.
    const int qt = gridDim.x - 1 - blockIdx.x;
    const int bh = blockIdx.y;
    const int q0 = qt * 128;
    const int tid = threadIdx.x;
    const int warpId = tid >> 5;
    const int lane = tid & 31;
    const int w16 = warpId * 16;

    const float* Qg = g_q + (size_t)bh * T_ * HD + (size_t)q0 * HD;
    const float* Kg = g_k + (size_t)bh * T_ * HD;
    const float* Vg = g_v + (size_t)bh * T_ * HD;

    // --- Row-index discovery fragment: frow.x[i] = row (0..15) of element i.
    // Robust against any accumulator layout: loaded from a memory image
    // where (r, c) = r.
    wmma::fragment<wmma::accumulator, 16, 16, 8, float> frow;
    for (int idx = lane; idx < 256; idx += 32) {
        int r = idx >> 4, c = idx & 15;
        Ss[(w16 + r) * 72 + c] = (float)r;
    }
    __syncwarp();
    wmma::load_matrix_sync(frow, &Ss[w16 * 72], 72, wmma::mem_row_major);
    __syncthreads();   // all warps done with the rowidx image before Q staging

    // --- Prologue: stage Q (128x64, pre-scaled) into Ss; K/V tile 0 -> buf 0.
#pragma unroll
    for (int i = 0; i < 8; i++) {
        int slot = tid + i * 256;        // 0..2047
        int r = slot >> 4;               // 0..127
        int c = (slot & 15) * 4;         // 0..60
        float4 v = *reinterpret_cast<const float4*>(&Qg[(size_t)r * HD + c]);
        Ss[r * 72 + c + 0] = wmma::__float_to_tf32(v.x * 0.125f);
        Ss[r * 72 + c + 1] = wmma::__float_to_tf32(v.y * 0.125f);
        Ss[r * 72 + c + 2] = wmma::__float_to_tf32(v.z * 0.125f);
        Ss[r * 72 + c + 3] = wmma::__float_to_tf32(v.w * 0.125f);
    }
#pragma unroll
    for (int i = 0; i < 4; i++) {
        int slot = tid + i * 256;        // 0..1023
        int r = slot >> 4;               // 0..63
        int c = (slot & 15) * 4;         // 0..60
        float4 kv = *reinterpret_cast<const float4*>(&Kg[(size_t)r * HD + c]);
        float4 vv = *reinterpret_cast<const float4*>(&Vg[(size_t)r * HD + c]);
        Kb[r * 72 + c + 0] = wmma::__float_to_tf32(kv.x);
        Kb[r * 72 + c + 1] = wmma::__float_to_tf32(kv.y);
        Kb[r * 72 + c + 2] = wmma::__float_to_tf32(kv.z);
        Kb[r * 72 + c + 3] = wmma::__float_to_tf32(kv.w);
        Vb[r * 72 + c + 0] = wmma::__float_to_tf32(vv.x);
        Vb[r * 72 + c + 1] = wmma::__float_to_tf32(vv.y);
        Vb[r * 72 + c + 2] = wmma::__float_to_tf32(vv.z);
        Vb[r * 72 + c + 3] = wmma::__float_to_tf32(vv.w);
    }
    __syncthreads();

    // Persistent Q fragments: warp's 16 rows x full K=64 (8 frags of 16x8)
    wmma::fragment<wmma::matrix_a, 16, 16, 8, wmma::precision::tf32, wmma::row_major> af_q[8];
#pragma unroll
    for (int kk = 0; kk < 8; kk++)
        wmma::load_matrix_sync(af_q[kk], &Ss[w16 * 72 + kk * 8], 72);

    // Persistent O accumulators: warp's 16 rows x 64 dims
    wmma::fragment<wmma::accumulator, 16, 16, 8, float> oacc[4];
#pragma unroll
    for (int j = 0; j < 4; j++)
        wmma::fill_fragment(oacc[j], 0.0f);

    // Softmax row ownership: 2 lanes per row (pairs share via shfl_xor(1))
    const int r = lane >> 1;             // 0..15 (row within warp's 16)
    const int half = lane & 1;           // column half: 0 -> cols 0..31, 1 -> 32..63
    const int grow = q0 + w16 + r;
    float m_i = -1e30f, l_i = 0.0f;

    const int nkt = (q0 + 128) >> 6;     // key tiles: 2*qt + 2

    for (int kb = 0; kb < nkt; kb++) {
        const int cur = kb & 1;
        float* Kc = Kb + cur * 64 * 72;
        float* Vc = Vb + cur * 64 * 72;
        float* Kn = Kb + (1 - cur) * 64 * 72;
        float* Vn = Vb + (1 - cur) * 64 * 72;
        const bool pf = (kb + 1 < nkt);

        // Issue next K tile's global loads (consumed mid-tile).
        float4 kreg[4];
        if (pf) {
#pragma unroll
            for (int i = 0; i < 4; i++) {
                int slot = tid + i * 256;
                int rr = slot >> 4;
                int cc = (slot & 15) * 4;
                kreg[i] = *reinterpret_cast<const float4*>(
                    &Kg[(size_t)((kb + 1) * 64 + rr) * HD + cc]);
            }
        }

        // --- S = Q K^T: warp's 16 rows x 64 keys ---
        {
            wmma::fragment<wmma::accumulator, 16, 16, 8, float> sacc[4];
#pragma unroll
            for (int j = 0; j < 4; j++)
                wmma::fill_fragment(sacc[j], 0.0f);
#pragma unroll
            for (int kk = 0; kk < 8; kk++) {
#pragma unroll
                for (int j = 0; j < 4; j++) {
                    wmma::fragment<wmma::matrix_b, 16, 16, 8, wmma::precision::tf32, wmma::col_major> bf;
                    // B(k, n) = K[n, k]: Kc[n*72 + k] => col_major, ldm 72
                    wmma::load_matrix_sync(bf, &Kc[(j * 16) * 72 + kk * 8], 72);
                    wmma::mma_sync(sacc[j], af_q[kk], bf, sacc[j]);
                }
            }
#pragma unroll
            for (int j = 0; j < 4; j++)
                wmma::store_matrix_sync(&Ss[w16 * 72 + j * 16],
                                        sacc[j], 72, wmma::mem_row_major);
        }
        __syncwarp();

        // Commit prefetched K into the free buffer; issue V prefetch loads.
        float4 vreg[4];
        if (pf) {
#pragma unroll
            for (int i = 0; i < 4; i++) {
                int slot = tid + i * 256;
                int rr = slot >> 4;
                int cc = (slot & 15) * 4;
                Kn[rr * 72 + cc + 0] = wmma::__float_to_tf32(kreg[i].x);
                Kn[rr * 72 + cc + 1] = wmma::__float_to_tf32(kreg[i].y);
                Kn[rr * 72 + cc + 2] = wmma::__float_to_tf32(kreg[i].z);
                Kn[rr * 72 + cc + 3] = wmma::__float_to_tf32(kreg[i].w);
            }
#pragma unroll
            for (int i = 0; i < 4; i++) {
                int slot = tid + i * 256;
                int rr = slot >> 4;
                int cc = (slot & 15) * 4;
                vreg[i] = *reinterpret_cast<const float4*>(
                    &Vg[(size_t)((kb + 1) * 64 + rr) * HD + cc]);
            }
        }

        // --- Online softmax (warp-local, 2 lanes/row; Q pre-scaled) ---
        float alpha;
        {
            float* srow = &Ss[(w16 + r) * 72 + half * 32];
            const int cb0 = kb * 64 + half * 32;

            float mloc = -1e30f;
#pragma unroll
            for (int i = 0; i < 8; i++) {
                float4 s4 = *reinterpret_cast<const float4*>(&srow[i * 4]);
                int cb = cb0 + i * 4;
                s4.x = (cb + 0 <= grow) ? s4.x : -1e30f;
                s4.y = (cb + 1 <= grow) ? s4.y : -1e30f;
                s4.z = (cb + 2 <= grow) ? s4.z : -1e30f;
                s4.w = (cb + 3 <= grow) ? s4.w : -1e30f;
                mloc = fmaxf(mloc, fmaxf(fmaxf(s4.x, s4.y), fmaxf(s4.z, s4.w)));
            }
            mloc = fmaxf(mloc, __shfl_xor_sync(0xffffffffu, mloc, 1));
            const float m_new = fmaxf(m_i, mloc);
            alpha = __expf(m_i - m_new);

            float ssum = 0.0f;
#pragma unroll
            for (int i = 0; i < 8; i++) {
                float4 s4 = *reinterpret_cast<const float4*>(&srow[i * 4]);
                int cb = cb0 + i * 4;
                float p0 = __expf(((cb + 0 <= grow) ? s4.x : -1e30f) - m_new);
                float p1 = __expf(((cb + 1 <= grow) ? s4.y : -1e30f) - m_new);
                float p2 = __expf(((cb + 2 <= grow) ? s4.z : -1e30f) - m_new);
                float p3 = __expf(((cb + 3 <= grow) ? s4.w : -1e30f) - m_new);
                ssum += (p0 + p1) + (p2 + p3);
                float4 pout;
                pout.x = wmma::__float_to_tf32(p0);
                pout.y = wmma::__float_to_tf32(p1);
                pout.z = wmma::__float_to_tf32(p2);
                pout.w = wmma::__float_to_tf32(p3);
                *reinterpret_cast<float4*>(&srow[i * 4]) = pout;
            }
            ssum += __shfl_xor_sync(0xffffffffu, ssum, 1);
            l_i = l_i * alpha + ssum;
            m_i = m_new;
        }

        // Rescale O register fragments by per-row alpha (rowidx + shfl).
        {
            float a_el[8];
#pragma unroll
            for (int i = 0; i < 8; i++)
                a_el[i] = __shfl_sync(0xffffffffu, alpha, ((int)frow.x[i]) << 1);
#pragma unroll
            for (int j = 0; j < 4; j++)
#pragma unroll
                for (int i = 0; i < 8; i++)
                    oacc[j].x[i] *= a_el[i];
        }
        __syncwarp();   // P stores visible before matrix_a loads below

        // --- O += P @ V: warp's 16 rows x 64 dims (accumulate in regs) ---
        {
#pragma unroll
            for (int kk = 0; kk < 8; kk++) {
                wmma::fragment<wmma::matrix_a, 16, 16, 8, wmma::precision::tf32, wmma::row_major> ap;
                wmma::load_matrix_sync(ap, &Ss[w16 * 72 + kk * 8], 72);
#pragma unroll
                for (int j = 0; j < 4; j++) {
                    wmma::fragment<wmma::matrix_b, 16, 16, 8, wmma::precision::tf32, wmma::row_major> bf;
                    wmma::load_matrix_sync(bf, &Vc[(kk * 8) * 72 + j * 16], 72);
                    wmma::mma_sync(oacc[j], ap, bf, oacc[j]);
                }
            }
        }

        // Commit prefetched V to the free buffer.
        if (pf) {
#pragma unroll
            for (int i = 0; i < 4; i++) {
                int slot = tid + i * 256;
                int rr = slot >> 4;
                int cc = (slot & 15) * 4;
                Vn[rr * 72 + cc + 0] = wmma::__float_to_tf32(vreg[i].x);
                Vn[rr * 72 + cc + 1] = wmma::__float_to_tf32(vreg[i].y);
                Vn[rr * 72 + cc + 2] = wmma::__float_to_tf32(vreg[i].z);
                Vn[rr * 72 + cc + 3] = wmma::__float_to_tf32(vreg[i].w);
            }
        }
        __syncthreads();   // sole block barrier: buffer swap safety
    }

    // --- Epilogue: normalize O by 1/l_i (per row) and write g_att ---
    {
        const float inv = 1.0f / l_i;    // valid on both lanes of each row pair
        float inv_el[8];
#pragma unroll
        for (int i = 0; i < 8; i++)
            inv_el[i] = __shfl_sync(0xffffffffu, inv, ((int)frow.x[i]) << 1);
#pragma unroll
        for (int j = 0; j < 4; j++) {
#pragma unroll
            for (int i = 0; i < 8; i++)
                oacc[j].x[i] *= inv_el[i];
            wmma::store_matrix_sync(&Ss[w16 * 72 + j * 16], oacc[j], 72,
                                    wmma::mem_row_major);
        }
    }
    __syncwarp();

    const int b = bh / H_;
    const int h = bh % H_;
    const float* orow = &Ss[(w16 + r) * 72 + half * 32];
    float* outp = g_att + ((size_t)(b * T_ + q0 + w16 + r)) * C_ + h * HD + half * 32;
#pragma unroll
    for (int i = 0; i < 8; i++)
        *reinterpret_cast<float4*>(&outp[i * 4]) =
            *reinterpret_cast<const float4*>(&orow[i * 4]);
}

// ---------------------------------------------------------------------------
extern "C" void kernel_launch(void* const* d_in, const int* in_sizes, int n_in,
                              void* d_out, int out_size)
{
    const float* x     = (const float*)d_in[0];   // (B,T,C)
    const float* Wqkv  = (const float*)d_in[1];   // (C, 3C)
    const float* bqkv  = (const float*)d_in[2];   // (3C,)
    const float* Wproj = (const float*)d_in[3];   // (C, C)
    const float* bproj = (const float*)d_in[4];   // (C,)
    float* out = (float*)d_out;                   // (B,T,C)

    cudaFuncSetAttribute(gemm_kernel, cudaFuncAttributeMaxDynamicSharedMemorySize,
                         GEMM_SMEM_BYTES);
    cudaFuncSetAttribute(attn_kernel, cudaFuncAttributeMaxDynamicSharedMemorySize,
                         ATTN_SMEM_BYTES);

    const int M = B_ * T_;   // 4096

    // 1) QKV projection + bias + scatter into (b,h,t,d) q/k/v buffers
    {
        dim3 grid(3 * C_ / 128, M / 128);  // (24, 32)
        gemm_kernel<<<grid, 256, GEMM_SMEM_BYTES>>>(
            x, Wqkv, bqkv, nullptr, 3 * C_, C_, /*mode=*/1);
    }

    // 2) Causal flash attention -> g_att (b,t,c)
    {
        dim3 grid(T_ / 128, B_ * H_);      // (16, 32)
        attn_kernel<<<grid, 256, ATTN_SMEM_BYTES>>>();
    }

    // 3) Output projection + bias -> d_out
    {
        dim3 grid(C_ / 128, M / 128);      // (8, 32)
        gemm_kernel<<<grid, 256, GEMM_SMEM_BYTES>>>(
            nullptr, Wproj, bproj, out, C_, C_, /*mode=*/0);
    }
}

// round 11
// speedup vs baseline: 1.1630x; 1.1630x over previous
#include <cuda_runtime.h>
#include <cuda_bf16.h>
#include <cstdint>
#include <mma.h>

using namespace nvcuda;

// Problem constants
#define B_  2
#define T_  2048
#define C_  1024
#define H_  16
#define HD  64

// Scratch (device globals: allocation-free per harness rules)
__device__ float g_q[(size_t)B_ * H_ * T_ * HD];   // (b,h,t,d), tf32-rounded
__device__ float g_k[(size_t)B_ * H_ * T_ * HD];   // tf32-rounded
__device__ float g_v[(size_t)B_ * H_ * T_ * HD];   // tf32-rounded
__device__ float g_att[(size_t)B_ * T_ * C_];      // (b,t,h*hd), tf32-rounded
__device__ float g_x [(size_t)B_ * T_ * C_];       // tf32-rounded x
__device__ float g_w1[(size_t)C_ * 3 * C_];        // tf32-rounded Wqkv
__device__ float g_w2[(size_t)C_ * C_];            // tf32-rounded Wproj

// ---------------------------------------------------------------------------
// Pre-rounding pass: dst[i] = tf32_rn(src[i]). Makes cp.async raw copies exact.
// ---------------------------------------------------------------------------
__global__ __launch_bounds__(256) void round_tf32_kernel(
    const float* __restrict__ src, float* __restrict__ dst, int n4)
{
    int i = blockIdx.x * blockDim.x + threadIdx.x;
    if (i < n4) {
        float4 v = reinterpret_cast<const float4*>(src)[i];
        v.x = wmma::__float_to_tf32(v.x);
        v.y = wmma::__float_to_tf32(v.y);
        v.z = wmma::__float_to_tf32(v.z);
        v.w = wmma::__float_to_tf32(v.w);
        reinterpret_cast<float4*>(dst)[i] = v;
    }
}

// ---------------------------------------------------------------------------
// cp.async helpers (LDGSTS, 16B)
// ---------------------------------------------------------------------------
__device__ __forceinline__ void cp_async16(void* smem_dst, const void* gmem_src) {
    unsigned int s = (unsigned int)__cvta_generic_to_shared(smem_dst);
    asm volatile("cp.async.cg.shared.global [%0], [%1], 16;\n"
                 :: "r"(s), "l"(gmem_src));
}
__device__ __forceinline__ void cp_async_commit() {
    asm volatile("cp.async.commit_group;\n");
}
__device__ __forceinline__ void cp_async_wait_all() {
    asm volatile("cp.async.wait_group 0;\n");
}

// ---------------------------------------------------------------------------
// GEMM: C[M,N] = A[M,K] @ W[K,N] + bias[N]
// BM=128, BN=128, BK=32, 256 threads (8 warps, 4x2 grid, 32x64 per warp)
// tf32 WMMA m16n16k8, fp32 accumulate. 2-stage cp.async pipeline, no
// register prefetch -> fits 2 CTAs/SM (launch_bounds(256,2)).
// Inputs must be pre-rounded to tf32 (raw-byte copies into SMEM).
// mode 0: write row-major to out (fp32).
// mode 1: scatter into g_q/g_k/g_v, tf32-rounded (consumed raw by attention).
// ---------------------------------------------------------------------------
#define GEMM_STAGE_FLOATS (128 * 40 + 32 * 136)          // 9472
#define GEMM_SMEM_BYTES   (2 * GEMM_STAGE_FLOATS * 4)    // 75776 (Cs = 69632 fits)

__global__ __launch_bounds__(256, 2) void gemm_kernel(
    const float* __restrict__ A,
    const float* __restrict__ W,
    const float* __restrict__ bias,
    float* __restrict__ out,
    int N, int K, int mode)
{
    extern __shared__ float smem[];
    float* Cs = smem;               // epilogue reuse: 128 x 136 fp32

    const int m0 = blockIdx.y * 128;
    const int n0 = blockIdx.x * 128;
    const int tid = threadIdx.x;
    const int warpId = tid >> 5;
    const int wr = warpId & 3;      // warp row (0..3) -> 32 rows each
    const int wc = warpId >> 2;     // warp col (0..1) -> 64 cols each

    wmma::fragment<wmma::accumulator, 16, 16, 8, float> acc[2][4];
#pragma unroll
    for (int i = 0; i < 2; i++)
#pragma unroll
        for (int j = 0; j < 4; j++)
            wmma::fill_fragment(acc[i][j], 0.0f);

    const int nk = K >> 5;          // K/32 stages

    // Stage issue: raw 16B copies (data pre-rounded to tf32).
    auto issue = [&](int k0, int s) {
        float* As = smem + s * GEMM_STAGE_FLOATS;   // 128 x 40
        float* Bs = As + 128 * 40;                  // 32 x 136
#pragma unroll
        for (int i = 0; i < 4; i++) {               // A: 128x32 = 1024 chunks
            int slot = tid + i * 256;
            int r = slot >> 3;
            int c = (slot & 7) * 4;
            cp_async16(&As[r * 40 + c], &A[(size_t)(m0 + r) * K + k0 + c]);
        }
#pragma unroll
        for (int i = 0; i < 4; i++) {               // B: 32x128 = 1024 chunks
            int slot = tid + i * 256;
            int r = slot >> 5;
            int c = (slot & 31) * 4;
            cp_async16(&Bs[r * 136 + c], &W[(size_t)(k0 + r) * N + n0 + c]);
        }
        cp_async_commit();
    };

    issue(0, 0);

    for (int ki = 0; ki < nk; ki++) {
        cp_async_wait_all();
        __syncthreads();            // stage ki visible; prev-iter MMA complete
        if (ki + 1 < nk)
            issue((ki + 1) * 32, (ki + 1) & 1);     // overlaps with MMA below

        const float* As = smem + (ki & 1) * GEMM_STAGE_FLOATS;
        const float* Bs = As + 128 * 40;

#pragma unroll
        for (int kk = 0; kk < 4; kk++) {
            wmma::fragment<wmma::matrix_a, 16, 16, 8, wmma::precision::tf32, wmma::row_major> af[2];
            wmma::fragment<wmma::matrix_b, 16, 16, 8, wmma::precision::tf32, wmma::row_major> bf[4];
#pragma unroll
            for (int i = 0; i < 2; i++)
                wmma::load_matrix_sync(af[i], &As[(wr * 32 + i * 16) * 40 + kk * 8], 40);
#pragma unroll
            for (int j = 0; j < 4; j++)
                wmma::load_matrix_sync(bf[j], &Bs[(kk * 8) * 136 + wc * 64 + j * 16], 136);
#pragma unroll
            for (int i = 0; i < 2; i++)
#pragma unroll
                for (int j = 0; j < 4; j++)
                    wmma::mma_sync(acc[i][j], af[i], bf[j], acc[i][j]);
        }
    }
    __syncthreads();                // all MMA reads done before Cs overwrite

    // Epilogue: stage accumulators in shared, then SIMT write with bias.
#pragma unroll
    for (int i = 0; i < 2; i++)
#pragma unroll
        for (int j = 0; j < 4; j++)
            wmma::store_matrix_sync(&Cs[(wr * 32 + i * 16) * 136 + wc * 64 + j * 16],
                                    acc[i][j], 136, wmma::mem_row_major);
    __syncthreads();

    if (mode == 0) {
#pragma unroll
        for (int i = 0; i < 64; i++) {
            int slot = tid + i * 256;   // 0..16383
            int r = slot >> 7;          // 0..127
            int c = slot & 127;         // 0..127
            out[(size_t)(m0 + r) * N + n0 + c] = Cs[r * 136 + c] + bias[n0 + c];
        }
    } else {
        // QKV scatter, tf32-rounded (attention cp.asyncs these raw).
        // Column n = n0 + c; head period 192 cols.
#pragma unroll
        for (int i = 0; i < 64; i++) {
            int slot = tid + i * 256;
            int r = slot >> 7;
            int c = slot & 127;
            int n = n0 + c;
            int h = n / 192;
            int rem = n - h * 192;
            int sel = rem >> 6;         // 0=q, 1=k, 2=v
            int d = rem & 63;
            float* dst = (sel == 0) ? g_q : (sel == 1) ? g_k : g_v;
            int m = m0 + r;
            int b = m >> 11;            // /T_
            int t = m & (T_ - 1);
            dst[(((size_t)(b * H_ + h)) * T_ + t) * HD + d] =
                wmma::__float_to_tf32(Cs[r * 136 + c] + bias[n]);
        }
    }
}

// ---------------------------------------------------------------------------
// Flash attention, FA2-style warp autonomy, register-resident O.
// CTA: 128 query rows for one (b,h); 8 warps, warp w owns rows [16w, 16w+16).
// Q persistent in matrix_a fragments (pre-scaled by 1/sqrt(hd)).
// O persistent in accumulator fragments; per-row alpha/inv applied via a
// one-time row-index discovery fragment + shfl (no layout assumptions).
// K/V tiles (64 keys) double-buffered in SMEM via raw cp.async (q/k/v are
// tf32-pre-rounded by the QKV GEMM). ONE __syncthreads per key tile.
// SMEM = 110592 B -> 2 CTA/SM. Output written tf32-rounded.
// ---------------------------------------------------------------------------
#define ATTN_SMEM_BYTES ((128 * 72 + 2 * 64 * 72 + 2 * 64 * 72) * 4)  // 110592

__global__ __launch_bounds__(256, 2) void attn_kernel()
{
    extern __shared__ float smem[];
    float* Ss = smem;                    // 128 x 72: Q staging, then S/P (warp-private rows)
    float* Kb = Ss + 128 * 72;           // 2 x 64 x 72 (key tiles, tf32)
    float* Vb = Kb + 2 * 64 * 72;        // 2 x 64 x 72 (value tiles, tf32)

    // Reverse order: heaviest query tiles scheduled first.
    const int qt = gridDim.x - 1 - blockIdx.x;
    const int bh = blockIdx.y;
    const int q0 = qt * 128;
    const int tid = threadIdx.x;
    const int warpId = tid >> 5;
    const int lane = tid & 31;
    const int w16 = warpId * 16;

    const float* Qg = g_q + (size_t)bh * T_ * HD + (size_t)q0 * HD;
    const float* Kg = g_k + (size_t)bh * T_ * HD;
    const float* Vg = g_v + (size_t)bh * T_ * HD;

    // --- Row-index discovery fragment: frow.x[i] = row (0..15) of element i.
    wmma::fragment<wmma::accumulator, 16, 16, 8, float> frow;
    for (int idx = lane; idx < 256; idx += 32) {
        int r = idx >> 4, c = idx & 15;
        Ss[(w16 + r) * 72 + c] = (float)r;
    }
    __syncwarp();
    wmma::load_matrix_sync(frow, &Ss[w16 * 72], 72, wmma::mem_row_major);
    __syncthreads();   // all warps done with the rowidx image before Q staging

    // --- Prologue: K/V tile 0 via raw cp.async; stage Q (scaled) into Ss.
#pragma unroll
    for (int i = 0; i < 4; i++) {
        int slot = tid + i * 256;        // 0..1023
        int r = slot >> 4;               // 0..63
        int c = (slot & 15) * 4;         // 0..60
        cp_async16(&Kb[r * 72 + c], &Kg[(size_t)r * HD + c]);
        cp_async16(&Vb[r * 72 + c], &Vg[(size_t)r * HD + c]);
    }
    cp_async_commit();

#pragma unroll
    for (int i = 0; i < 8; i++) {
        int slot = tid + i * 256;        // 0..2047
        int r = slot >> 4;               // 0..127
        int c = (slot & 15) * 4;         // 0..60
        float4 v = *reinterpret_cast<const float4*>(&Qg[(size_t)r * HD + c]);
        // q pre-rounded; 0.125 is a power of two so the product is exact tf32
        Ss[r * 72 + c + 0] = v.x * 0.125f;
        Ss[r * 72 + c + 1] = v.y * 0.125f;
        Ss[r * 72 + c + 2] = v.z * 0.125f;
        Ss[r * 72 + c + 3] = v.w * 0.125f;
    }
    cp_async_wait_all();
    __syncthreads();

    // Persistent Q fragments: warp's 16 rows x full K=64 (8 frags of 16x8)
    wmma::fragment<wmma::matrix_a, 16, 16, 8, wmma::precision::tf32, wmma::row_major> af_q[8];
#pragma unroll
    for (int kk = 0; kk < 8; kk++)
        wmma::load_matrix_sync(af_q[kk], &Ss[w16 * 72 + kk * 8], 72);

    // Persistent O accumulators: warp's 16 rows x 64 dims
    wmma::fragment<wmma::accumulator, 16, 16, 8, float> oacc[4];
#pragma unroll
    for (int j = 0; j < 4; j++)
        wmma::fill_fragment(oacc[j], 0.0f);

    // Softmax row ownership: 2 lanes per row (pairs share via shfl_xor(1))
    const int r = lane >> 1;             // 0..15 (row within warp's 16)
    const int half = lane & 1;           // column half: 0 -> cols 0..31, 1 -> 32..63
    const int grow = q0 + w16 + r;
    float m_i = -1e30f, l_i = 0.0f;

    const int nkt = (q0 + 128) >> 6;     // key tiles: 2*qt + 2

    for (int kb = 0; kb < nkt; kb++) {
        const int cur = kb & 1;
        float* Kc = Kb + cur * 64 * 72;
        float* Vc = Vb + cur * 64 * 72;
        const bool pf = (kb + 1 < nkt);

        // Issue next K/V tile as raw cp.async into the free buffer.
        if (pf) {
            float* Kn = Kb + (1 - cur) * 64 * 72;
            float* Vn = Vb + (1 - cur) * 64 * 72;
#pragma unroll
            for (int i = 0; i < 4; i++) {
                int slot = tid + i * 256;
                int rr = slot >> 4;
                int cc = (slot & 15) * 4;
                cp_async16(&Kn[rr * 72 + cc],
                           &Kg[(size_t)((kb + 1) * 64 + rr) * HD + cc]);
                cp_async16(&Vn[rr * 72 + cc],
                           &Vg[(size_t)((kb + 1) * 64 + rr) * HD + cc]);
            }
            cp_async_commit();
        }

        // --- S = Q K^T: warp's 16 rows x 64 keys ---
        {
            wmma::fragment<wmma::accumulator, 16, 16, 8, float> sacc[4];
#pragma unroll
            for (int j = 0; j < 4; j++)
                wmma::fill_fragment(sacc[j], 0.0f);
#pragma unroll
            for (int kk = 0; kk < 8; kk++) {
#pragma unroll
                for (int j = 0; j < 4; j++) {
                    wmma::fragment<wmma::matrix_b, 16, 16, 8, wmma::precision::tf32, wmma::col_major> bf;
                    wmma::load_matrix_sync(bf, &Kc[(j * 16) * 72 + kk * 8], 72);
                    wmma::mma_sync(sacc[j], af_q[kk], bf, sacc[j]);
                }
            }
#pragma unroll
            for (int j = 0; j < 4; j++)
                wmma::store_matrix_sync(&Ss[w16 * 72 + j * 16],
                                        sacc[j], 72, wmma::mem_row_major);
        }
        __syncwarp();

        // --- Online softmax (warp-local, 2 lanes/row; Q pre-scaled) ---
        float alpha;
        {
            float* srow = &Ss[(w16 + r) * 72 + half * 32];
            const int cb0 = kb * 64 + half * 32;

            float mloc = -1e30f;
#pragma unroll
            for (int i = 0; i < 8; i++) {
                float4 s4 = *reinterpret_cast<const float4*>(&srow[i * 4]);
                int cb = cb0 + i * 4;
                s4.x = (cb + 0 <= grow) ? s4.x : -1e30f;
                s4.y = (cb + 1 <= grow) ? s4.y : -1e30f;
                s4.z = (cb + 2 <= grow) ? s4.z : -1e30f;
                s4.w = (cb + 3 <= grow) ? s4.w : -1e30f;
                mloc = fmaxf(mloc, fmaxf(fmaxf(s4.x, s4.y), fmaxf(s4.z, s4.w)));
            }
            mloc = fmaxf(mloc, __shfl_xor_sync(0xffffffffu, mloc, 1));
            const float m_new = fmaxf(m_i, mloc);
            alpha = __expf(m_i - m_new);

            float ssum = 0.0f;
#pragma unroll
            for (int i = 0; i < 8; i++) {
                float4 s4 = *reinterpret_cast<const float4*>(&srow[i * 4]);
                int cb = cb0 + i * 4;
                float p0 = __expf(((cb + 0 <= grow) ? s4.x : -1e30f) - m_new);
                float p1 = __expf(((cb + 1 <= grow) ? s4.y : -1e30f) - m_new);
                float p2 = __expf(((cb + 2 <= grow) ? s4.z : -1e30f) - m_new);
                float p3 = __expf(((cb + 3 <= grow) ? s4.w : -1e30f) - m_new);
                ssum += (p0 + p1) + (p2 + p3);
                float4 pout;
                pout.x = wmma::__float_to_tf32(p0);
                pout.y = wmma::__float_to_tf32(p1);
                pout.z = wmma::__float_to_tf32(p2);
                pout.w = wmma::__float_to_tf32(p3);
                *reinterpret_cast<float4*>(&srow[i * 4]) = pout;
            }
            ssum += __shfl_xor_sync(0xffffffffu, ssum, 1);
            l_i = l_i * alpha + ssum;
            m_i = m_new;
        }

        // Rescale O register fragments by per-row alpha (rowidx + shfl).
        {
            float a_el[8];
#pragma unroll
            for (int i = 0; i < 8; i++)
                a_el[i] = __shfl_sync(0xffffffffu, alpha, ((int)frow.x[i]) << 1);
#pragma unroll
            for (int j = 0; j < 4; j++)
#pragma unroll
                for (int i = 0; i < 8; i++)
                    oacc[j].x[i] *= a_el[i];
        }
        __syncwarp();   // P stores visible before matrix_a loads below

        // --- O += P @ V: warp's 16 rows x 64 dims (accumulate in regs) ---
        {
#pragma unroll
            for (int kk = 0; kk < 8; kk++) {
                wmma::fragment<wmma::matrix_a, 16, 16, 8, wmma::precision::tf32, wmma::row_major> ap;
                wmma::load_matrix_sync(ap, &Ss[w16 * 72 + kk * 8], 72);
#pragma unroll
                for (int j = 0; j < 4; j++) {
                    wmma::fragment<wmma::matrix_b, 16, 16, 8, wmma::precision::tf32, wmma::row_major> bf;
                    wmma::load_matrix_sync(bf, &Vc[(kk * 8) * 72 + j * 16], 72);
                    wmma::mma_sync(oacc[j], ap, bf, oacc[j]);
                }
            }
        }

        if (pf) cp_async_wait_all();   // next K/V tile landed
        __syncthreads();               // sole block barrier: buffer swap safety
    }

    // --- Epilogue: normalize O by 1/l_i and write g_att (tf32-rounded) ---
    {
        const float inv = 1.0f / l_i;    // valid on both lanes of each row pair
        float inv_el[8];
#pragma unroll
        for (int i = 0; i < 8; i++)
            inv_el[i] = __shfl_sync(0xffffffffu, inv, ((int)frow.x[i]) << 1);
#pragma unroll
        for (int j = 0; j < 4; j++) {
#pragma unroll
            for (int i = 0; i < 8; i++)
                oacc[j].x[i] = wmma::__float_to_tf32(oacc[j].x[i] * inv_el[i]);
            wmma::store_matrix_sync(&Ss[w16 * 72 + j * 16], oacc[j], 72,
                                    wmma::mem_row_major);
        }
    }
    __syncwarp();

    const int b = bh / H_;
    const int h = bh % H_;
    const float* orow = &Ss[(w16 + r) * 72 + half * 32];
    float* outp = g_att + ((size_t)(b * T_ + q0 + w16 + r)) * C_ + h * HD + half * 32;
#pragma unroll
    for (int i = 0; i < 8; i++)
        *reinterpret_cast<float4*>(&outp[i * 4]) =
            *reinterpret_cast<const float4*>(&orow[i * 4]);
}

// ---------------------------------------------------------------------------
extern "C" void kernel_launch(void* const* d_in, const int* in_sizes, int n_in,
                              void* d_out, int out_size)
{
    const float* x     = (const float*)d_in[0];   // (B,T,C)
    const float* Wqkv  = (const float*)d_in[1];   // (C, 3C)
    const float* bqkv  = (const float*)d_in[2];   // (3C,)
    const float* Wproj = (const float*)d_in[3];   // (C, C)
    const float* bproj = (const float*)d_in[4];   // (C,)
    float* out = (float*)d_out;                   // (B,T,C)

    cudaFuncSetAttribute(gemm_kernel, cudaFuncAttributeMaxDynamicSharedMemorySize,
                         GEMM_SMEM_BYTES);
    cudaFuncSetAttribute(attn_kernel, cudaFuncAttributeMaxDynamicSharedMemorySize,
                         ATTN_SMEM_BYTES);

    const int M = B_ * T_;   // 4096

    // 0) Pre-round inputs to tf32 (exactness of raw cp.async copies)
    {
        float* px;  cudaGetSymbolAddress((void**)&px,  g_x);
        float* pw1; cudaGetSymbolAddress((void**)&pw1, g_w1);
        float* pw2; cudaGetSymbolAddress((void**)&pw2, g_w2);
        int n1 = B_ * T_ * C_ / 4;        // 1048576
        int n2 = C_ * 3 * C_ / 4;         // 786432
        int n3 = C_ * C_ / 4;             // 262144
        round_tf32_kernel<<<(n1 + 255) / 256, 256>>>(x, px, n1);
        round_tf32_kernel<<<(n2 + 255) / 256, 256>>>(Wqkv, pw1, n2);
        round_tf32_kernel<<<(n3 + 255) / 256, 256>>>(Wproj, pw2, n3);
    }

    float* px;  cudaGetSymbolAddress((void**)&px,  g_x);
    float* pw1; cudaGetSymbolAddress((void**)&pw1, g_w1);
    float* pw2; cudaGetSymbolAddress((void**)&pw2, g_w2);
    float* patt; cudaGetSymbolAddress((void**)&patt, g_att);

    // 1) QKV projection + bias + scatter into (b,h,t,d) q/k/v (tf32-rounded)
    {
        dim3 grid(3 * C_ / 128, M / 128);  // (24, 32)
        gemm_kernel<<<grid, 256, GEMM_SMEM_BYTES>>>(
            px, pw1, bqkv, nullptr, 3 * C_, C_, /*mode=*/1);
    }

    // 2) Causal flash attention -> g_att (b,t,c), tf32-rounded
    {
        dim3 grid(T_ / 128, B_ * H_);      // (16, 32)
        attn_kernel<<<grid, 256, ATTN_SMEM_BYTES>>>();
    }

    // 3) Output projection + bias -> d_out
    {
        dim3 grid(C_ / 128, M / 128);      // (8, 32)
        gemm_kernel<<<grid, 256, GEMM_SMEM_BYTES>>>(
            patt, pw2, bproj, out, C_, C_, /*mode=*/0);
    }
}